// round 2
// baseline (speedup 1.0000x reference)
#include <cuda_runtime.h>
#include <math.h>

#define NMAX 100000
#define EMAX 1600000
#define FD 128
#define HD 128
#define CD 40
#define NLAY 4

// ---- static device scratch (no allocations allowed) ----
__device__ float g_xw[(size_t)NMAX * HD];             // current layer x@W
__device__ float g_agg[NLAY][(size_t)NMAX * HD];      // per-layer pre-BN conv output
__device__ int   g_cnt[NMAX];
__device__ float g_dinv[NMAX];
__device__ int   g_off[NMAX + 1];
__device__ int   g_cur[NMAX];
__device__ int   g_csrc[EMAX];
__device__ float g_cval[EMAX];
__device__ float g_stats[NLAY][2 * HD];               // col sums / sumsq
__device__ float g_scale[NLAY][HD];                   // fused BN scale
__device__ float g_sbias[NLAY][HD];                   // fused BN bias
__device__ int   g_done[NLAY];                        // last-block-done counters

// ---- packed f32x2 helpers (sm_103a FFMA2 path; 2x fp32 FMA throughput) ----
__device__ __forceinline__ unsigned long long pk2(float lo, float hi) {
    unsigned long long r;
    asm("mov.b64 %0, {%1, %2};" : "=l"(r) : "f"(lo), "f"(hi));
    return r;
}
__device__ __forceinline__ void fma2(unsigned long long& d,
                                     unsigned long long a, unsigned long long b) {
    asm("fma.rn.f32x2 %0, %1, %2, %0;" : "+l"(d) : "l"(a), "l"(b));
}
__device__ __forceinline__ float2 up2(unsigned long long v) {
    float2 r;
    asm("mov.b64 {%0, %1}, %2;" : "=f"(r.x), "=f"(r.y) : "l"(v));
    return r;
}

// ---------------------------------------------------------------------------
__global__ void k_init(int n) {
    int i = blockIdx.x * blockDim.x + threadIdx.x;
    if (i < n) g_cnt[i] = 0;
    if (i < NLAY * 2 * HD) ((float*)g_stats)[i] = 0.0f;
    if (i < NLAY) g_done[i] = 0;
}

__global__ void k_hist(const int* __restrict__ dst, int e) {
    int i = blockIdx.x * blockDim.x + threadIdx.x;
    if (i < e) atomicAdd(&g_cnt[dst[i]], 1);
}

// single-block scan: offsets, cursor init, dinv
__global__ void k_scan(int n) {
    __shared__ int sp[1024];
    int t = threadIdx.x;
    int chunk = (n + 1023) >> 10;
    int beg = t * chunk;
    int end = min(beg + chunk, n);
    int s = 0;
    for (int j = beg; j < end; j++) s += g_cnt[j];
    sp[t] = s;
    __syncthreads();
    for (int d = 1; d < 1024; d <<= 1) {
        int tmp = (t >= d) ? sp[t - d] : 0;
        __syncthreads();
        sp[t] += tmp;
        __syncthreads();
    }
    int base = sp[t] - s;  // exclusive
    for (int j = beg; j < end; j++) {
        g_off[j] = base;
        g_cur[j] = base;
        g_dinv[j] = rsqrtf((float)g_cnt[j] + 2.0f);
        base += g_cnt[j];
    }
    if (end == n) g_off[n] = base;
}

__global__ void k_fill(const int* __restrict__ src, const int* __restrict__ dst, int e) {
    int i = blockIdx.x * blockDim.x + threadIdx.x;
    if (i < e) {
        int d = dst[i];
        int s = src[i];
        int p = atomicAdd(&g_cur[d], 1);
        g_csrc[p] = s;
        g_cval[p] = g_dinv[s];
    }
}

// ---------------------------------------------------------------------------
// SGEMM: g_xw[n,128] = A[n,128] @ W[128,128]
// A = x (layer 0) or relu(g_agg[layer-1]*scale+bias) fused on load.
// Inner loop uses packed fma.rn.f32x2 (2x fp32 rate vs scalar FFMA on sm_103a).
__global__ __launch_bounds__(256) void k_gemm(const float* __restrict__ x,
                                              const float* __restrict__ W,
                                              int layer, int n) {
    __shared__ __align__(16) float As[8][128];
    __shared__ __align__(16) float Bs[8][128];
    const float* A  = (layer == 0) ? x : g_agg[layer - 1];
    const float* sc = (layer > 0) ? g_scale[layer - 1] : 0;
    const float* sb = (layer > 0) ? g_sbias[layer - 1] : 0;
    int tid  = threadIdx.x;
    int trow = tid >> 4, tcol = tid & 15;
    int arow = tid >> 1, acol = (tid & 1) * 4;
    int brow = tid >> 5, bcol = (tid & 31) * 4;
    int row0 = blockIdx.x * 128;

    unsigned long long acc2[8][4];
#pragma unroll
    for (int m = 0; m < 8; m++)
#pragma unroll
        for (int q = 0; q < 4; q++) acc2[m][q] = 0ull;

    for (int k0 = 0; k0 < 128; k0 += 8) {
        int gr = row0 + arow;
        float4 a4 = make_float4(0.f, 0.f, 0.f, 0.f);
        if (gr < n) a4 = *(const float4*)(A + (size_t)gr * HD + k0 + acol);
        if (layer > 0) {
            int kb = k0 + acol;
            a4.x = fmaxf(fmaf(a4.x, sc[kb + 0], sb[kb + 0]), 0.f);
            a4.y = fmaxf(fmaf(a4.y, sc[kb + 1], sb[kb + 1]), 0.f);
            a4.z = fmaxf(fmaf(a4.z, sc[kb + 2], sb[kb + 2]), 0.f);
            a4.w = fmaxf(fmaf(a4.w, sc[kb + 3], sb[kb + 3]), 0.f);
        }
        As[acol + 0][arow] = a4.x;
        As[acol + 1][arow] = a4.y;
        As[acol + 2][arow] = a4.z;
        As[acol + 3][arow] = a4.w;
        *(float4*)&Bs[brow][bcol] =
            *(const float4*)(W + (size_t)(k0 + brow) * HD + bcol);
        __syncthreads();
#pragma unroll
        for (int k = 0; k < 8; k++) {
            float4 ra0 = *(const float4*)&As[k][trow * 8];
            float4 ra1 = *(const float4*)&As[k][trow * 8 + 4];
            float4 rb0 = *(const float4*)&Bs[k][tcol * 8];
            float4 rb1 = *(const float4*)&Bs[k][tcol * 8 + 4];
            unsigned long long b2[4];
            b2[0] = pk2(rb0.x, rb0.y); b2[1] = pk2(rb0.z, rb0.w);
            b2[2] = pk2(rb1.x, rb1.y); b2[3] = pk2(rb1.z, rb1.w);
            float ra[8] = {ra0.x, ra0.y, ra0.z, ra0.w, ra1.x, ra1.y, ra1.z, ra1.w};
#pragma unroll
            for (int m = 0; m < 8; m++) {
                unsigned long long ad = pk2(ra[m], ra[m]);
#pragma unroll
                for (int q = 0; q < 4; q++) fma2(acc2[m][q], ad, b2[q]);
            }
        }
        __syncthreads();
    }
#pragma unroll
    for (int m = 0; m < 8; m++) {
        int r = row0 + trow * 8 + m;
        if (r < n) {
            float2 c0 = up2(acc2[m][0]), c1 = up2(acc2[m][1]);
            float2 c2 = up2(acc2[m][2]), c3 = up2(acc2[m][3]);
            *(float4*)(g_xw + (size_t)r * HD + tcol * 8) =
                make_float4(c0.x, c0.y, c1.x, c1.y);
            *(float4*)(g_xw + (size_t)r * HD + tcol * 8 + 4) =
                make_float4(c2.x, c2.y, c3.x, c3.y);
        }
    }
}

// ---------------------------------------------------------------------------
// Aggregation: warp per node; lane owns 4 columns. Accumulates BN stats and,
// in the last block to finish, computes the fused BN scale/bias (k_fin fused).
__global__ __launch_bounds__(256) void k_agg(int layer, const float* __restrict__ convb,
                                             const float* __restrict__ bn_g,
                                             const float* __restrict__ bn_b, int n) {
    __shared__ float s_sum[128], s_sq[128];
    __shared__ int s_last;
    int tid = threadIdx.x;
    if (tid < 128) { s_sum[tid] = 0.f; s_sq[tid] = 0.f; }
    __syncthreads();

    int lane = tid & 31;
    int warp = tid >> 5;
    int c4 = lane * 4;
    float4 b4 = *(const float4*)(convb + c4);
    float* out = g_agg[layer];

    int gw = blockIdx.x * 8 + warp;
    int nw = gridDim.x * 8;

    float ls0 = 0.f, ls1 = 0.f, ls2 = 0.f, ls3 = 0.f;
    float lq0 = 0.f, lq1 = 0.f, lq2 = 0.f, lq3 = 0.f;

    for (int v = gw; v < n; v += nw) {
        int r0 = g_off[v], r1 = g_off[v + 1];
        float dv = g_dinv[v];
        unsigned long long p0 = 0ull, p1 = 0ull;  // packed (c0,c1),(c2,c3)
        int j = r0;
        for (; j + 1 < r1; j += 2) {
            int   s0 = g_csrc[j],   s1 = g_csrc[j + 1];
            float w0 = g_cval[j],   w1 = g_cval[j + 1];
            float4 x0 = *(const float4*)(g_xw + (size_t)s0 * HD + c4);
            float4 x1 = *(const float4*)(g_xw + (size_t)s1 * HD + c4);
            unsigned long long wd0 = pk2(w0, w0), wd1 = pk2(w1, w1);
            fma2(p0, wd0, pk2(x0.x, x0.y)); fma2(p1, wd0, pk2(x0.z, x0.w));
            fma2(p0, wd1, pk2(x1.x, x1.y)); fma2(p1, wd1, pk2(x1.z, x1.w));
        }
        if (j < r1) {
            int s0 = g_csrc[j]; float w0 = g_cval[j];
            float4 x0 = *(const float4*)(g_xw + (size_t)s0 * HD + c4);
            unsigned long long wd0 = pk2(w0, w0);
            fma2(p0, wd0, pk2(x0.x, x0.y)); fma2(p1, wd0, pk2(x0.z, x0.w));
        }
        float2 e0 = up2(p0), e1 = up2(p1);
        float4 xv = *(const float4*)(g_xw + (size_t)v * HD + c4);
        float t2 = 2.f * dv * dv;
        float a0 = fmaf(dv, e0.x, fmaf(t2, xv.x, b4.x));
        float a1 = fmaf(dv, e0.y, fmaf(t2, xv.y, b4.y));
        float a2 = fmaf(dv, e1.x, fmaf(t2, xv.z, b4.z));
        float a3 = fmaf(dv, e1.y, fmaf(t2, xv.w, b4.w));
        *(float4*)(out + (size_t)v * HD + c4) = make_float4(a0, a1, a2, a3);
        ls0 += a0; ls1 += a1; ls2 += a2; ls3 += a3;
        lq0 = fmaf(a0, a0, lq0); lq1 = fmaf(a1, a1, lq1);
        lq2 = fmaf(a2, a2, lq2); lq3 = fmaf(a3, a3, lq3);
    }
    atomicAdd(&s_sum[c4 + 0], ls0); atomicAdd(&s_sum[c4 + 1], ls1);
    atomicAdd(&s_sum[c4 + 2], ls2); atomicAdd(&s_sum[c4 + 3], ls3);
    atomicAdd(&s_sq[c4 + 0], lq0);  atomicAdd(&s_sq[c4 + 1], lq1);
    atomicAdd(&s_sq[c4 + 2], lq2);  atomicAdd(&s_sq[c4 + 3], lq3);
    __syncthreads();
    if (tid < 128) {
        atomicAdd(&g_stats[layer][tid], s_sum[tid]);
        atomicAdd(&g_stats[layer][128 + tid], s_sq[tid]);
    }
    // last-block-done: compute fused BN scale/bias
    __threadfence();
    __syncthreads();
    if (tid == 0) {
        int p = atomicAdd(&g_done[layer], 1);
        s_last = (p == (int)gridDim.x - 1);
    }
    __syncthreads();
    if (s_last && tid < 128) {
        __threadfence();
        float sum = g_stats[layer][tid];
        float sq  = g_stats[layer][tid + 128];
        float inv_n = 1.0f / (float)n;
        float mean = sum * inv_n;
        float var  = fmaxf(sq * inv_n - mean * mean, 0.f);
        float s = bn_g[layer * HD + tid] * rsqrtf(var + 1e-5f);
        g_scale[layer][tid] = s;
        g_sbias[layer][tid] = bn_b[layer * HD + tid] - mean * s;
    }
}

// ---------------------------------------------------------------------------
// JK head + fused log_softmax: out[n,40] = log_softmax(sum_i relu_bn(h_i) @ fc_w[i] + b)
// Single GEMM over concatenated K=640, BN+ReLU fused on A load, packed FFMA2,
// row-softmax via 8-lane shuffle groups, writes final result directly.
__global__ __launch_bounds__(256) void k_jk(const float* __restrict__ x,
                                            const float* __restrict__ fw,
                                            const float* __restrict__ fb,
                                            float* __restrict__ outp, int n) {
    __shared__ __align__(16) float As[16][128];
    __shared__ __align__(16) float Bs[16][40];
    __shared__ float bsum[40];
    int tid = threadIdx.x;
    if (tid < 40) {
        float b = 0.f;
        for (int i = 0; i < NLAY + 1; i++) b += fb[i * CD + tid];
        bsum[tid] = b;
    }
    int trow = tid >> 3, tcol = tid & 7;
    int row0 = blockIdx.x * 128;
    // packed over row pairs: acc01[c] = rows(trow*4+0, +1), acc23[c] = rows(+2, +3)
    unsigned long long acc01[5], acc23[5];
#pragma unroll
    for (int c = 0; c < 5; c++) { acc01[c] = 0ull; acc23[c] = 0ull; }

    for (int k0 = 0; k0 < 640; k0 += 16) {
        int L = k0 >> 7;
        int kbase = k0 & 127;
        const float* A = (L == 0) ? x : g_agg[L - 1];
#pragma unroll
        for (int v = 0; v < 2; v++) {
            int id = tid + v * 256;
            int r = id >> 2;
            int kq = (id & 3) * 4;
            int gr = row0 + r;
            float4 a4 = make_float4(0.f, 0.f, 0.f, 0.f);
            if (gr < n) a4 = *(const float4*)(A + (size_t)gr * HD + kbase + kq);
            if (L > 0) {
                int kk = kbase + kq;
                a4.x = fmaxf(fmaf(a4.x, g_scale[L - 1][kk + 0], g_sbias[L - 1][kk + 0]), 0.f);
                a4.y = fmaxf(fmaf(a4.y, g_scale[L - 1][kk + 1], g_sbias[L - 1][kk + 1]), 0.f);
                a4.z = fmaxf(fmaf(a4.z, g_scale[L - 1][kk + 2], g_sbias[L - 1][kk + 2]), 0.f);
                a4.w = fmaxf(fmaf(a4.w, g_scale[L - 1][kk + 3], g_sbias[L - 1][kk + 3]), 0.f);
            }
            As[kq + 0][r] = a4.x;
            As[kq + 1][r] = a4.y;
            As[kq + 2][r] = a4.z;
            As[kq + 3][r] = a4.w;
        }
        if (tid < 160) {
            int kr = tid / 10;
            int nc = (tid % 10) * 4;
            int kk = kbase + kr;
            *(float4*)&Bs[kr][nc] =
                *(const float4*)(fw + ((size_t)L * HD + kk) * CD + nc);
        }
        __syncthreads();
#pragma unroll
        for (int k = 0; k < 16; k++) {
            float ra[4], rb[5];
#pragma unroll
            for (int m = 0; m < 4; m++) ra[m] = As[k][trow * 4 + m];
#pragma unroll
            for (int c = 0; c < 5; c++) rb[c] = Bs[k][tcol * 5 + c];
            unsigned long long a01 = pk2(ra[0], ra[1]);
            unsigned long long a23 = pk2(ra[2], ra[3]);
#pragma unroll
            for (int c = 0; c < 5; c++) {
                unsigned long long bd = pk2(rb[c], rb[c]);
                fma2(acc01[c], a01, bd);
                fma2(acc23[c], a23, bd);
            }
        }
        __syncthreads();
    }
    // epilogue: add bias, row log-softmax across the 8 tcol threads of this trow
    float v[4][5];
#pragma unroll
    for (int c = 0; c < 5; c++) {
        float2 r01 = up2(acc01[c]);
        float2 r23 = up2(acc23[c]);
        float bb = bsum[tcol * 5 + c];
        v[0][c] = r01.x + bb; v[1][c] = r01.y + bb;
        v[2][c] = r23.x + bb; v[3][c] = r23.y + bb;
    }
#pragma unroll
    for (int m = 0; m < 4; m++) {
        int r = row0 + trow * 4 + m;
        float mx = v[m][0];
#pragma unroll
        for (int c = 1; c < 5; c++) mx = fmaxf(mx, v[m][c]);
#pragma unroll
        for (int d = 1; d < 8; d <<= 1) mx = fmaxf(mx, __shfl_xor_sync(0xffffffffu, mx, d));
        float s = 0.f;
#pragma unroll
        for (int c = 0; c < 5; c++) s += expf(v[m][c] - mx);
#pragma unroll
        for (int d = 1; d < 8; d <<= 1) s += __shfl_xor_sync(0xffffffffu, s, d);
        float ls = mx + logf(s);
        if (r < n) {
#pragma unroll
            for (int c = 0; c < 5; c++)
                outp[(size_t)r * CD + tcol * 5 + c] = v[m][c] - ls;
        }
    }
}

// ---------------------------------------------------------------------------
extern "C" void kernel_launch(void* const* d_in, const int* in_sizes, int n_in,
                              void* d_out, int out_size) {
    const float* x      = (const float*)d_in[0];
    const int*   ei     = (const int*)d_in[1];
    const float* conv_w = (const float*)d_in[2];
    const float* conv_b = (const float*)d_in[3];
    const float* bn_g   = (const float*)d_in[4];
    const float* bn_b   = (const float*)d_in[5];
    const float* fc_w   = (const float*)d_in[6];
    const float* fc_b   = (const float*)d_in[7];
    int n = in_sizes[0] / FD;
    int e = in_sizes[1] / 2;
    const int* src = ei;
    const int* dst = ei + e;

    k_init<<<(n + 255) / 256, 256>>>(n);
    k_hist<<<(e + 255) / 256, 256>>>(dst, e);
    k_scan<<<1, 1024>>>(n);
    k_fill<<<(e + 255) / 256, 256>>>(src, dst, e);

    int gblocks = (n + 127) / 128;
    for (int l = 0; l < NLAY; l++) {
        k_gemm<<<gblocks, 256>>>(x, conv_w + (size_t)l * FD * HD, l, n);
        k_agg<<<1480, 256>>>(l, conv_b + (size_t)l * HD, bn_g, bn_b, n);
    }
    k_jk<<<gblocks, 256>>>(x, fc_w, fc_b, (float*)d_out, n);
}